// round 5
// baseline (speedup 1.0000x reference)
#include <cuda_runtime.h>
#include <cstdint>

// Problem constants
#define NF 8
#define NK 16
#define NY 16
#define NX 16
#define NP 32
#define NT 8
#define NB 64
#define VOL (NY*NX*NP*NT)       // 65536 per (b,f)
#define COLS (NY*NX*NP)         // 8192 (y,x,p) points per (b,f)
#define CHUNKS 4
#define PTS (COLS/CHUNKS)       // 2048 points per chunk
#define JITER (PTS/256)         // 8 mainloop iterations
#define YXC (PTS/NP)            // 64 yx per chunk
#define STAGES 4

// Dynamic smem layout (bytes)
#define SB_P_OFF   0                         // 4 stages * 512 float4 = 32 KB
#define SB_Q_OFF   (STAGES*512*16)           // 32 KB
#define S_CL_OFF   (2*STAGES*512*16)         // 4 KB
#define S_R2_OFF   (S_CL_OFF + YXC*NK*4)     // 128 B
#define S_RED_OFF  (S_R2_OFF + 128)          // 512 B
#define SMEM_BYTES (S_RED_OFF + 8*NK*4)

// Precomputed tables (device globals — no allocation allowed)
__device__ float g_klat[NF*NK*NY];
__device__ float g_klon[NF*NK*NX];
__device__ float g_klev[NF*NK*NP];
__device__ float g_r[NF*NK];          // geometric ratio exp(-1/tau)
__device__ float g_ipart[NF*NK*4];    // 4 non-atomic integration partials per (f,k)

using u64 = unsigned long long;

// Packed f32x2 helpers (B300 packed fp32 pipe)
__device__ __forceinline__ u64 pk2(float lo, float hi) {
    u64 r; asm("mov.b64 %0,{%1,%2};" : "=l"(r) : "f"(lo), "f"(hi)); return r;
}
__device__ __forceinline__ u64 fma2(u64 a, u64 b, u64 c) {
    u64 d; asm("fma.rn.f32x2 %0,%1,%2,%3;" : "=l"(d) : "l"(a), "l"(b), "l"(c)); return d;
}
__device__ __forceinline__ u64 mul2(u64 a, u64 b) {
    u64 d; asm("mul.rn.f32x2 %0,%1,%2;" : "=l"(d) : "l"(a), "l"(b)); return d;
}
__device__ __forceinline__ float2 up2(u64 a) {
    float2 v; asm("mov.b64 {%0,%1},%2;" : "=f"(v.x), "=f"(v.y) : "l"(a)); return v;
}

// cp.async helpers (16B, L2-only)
__device__ __forceinline__ void cp16(void* dst_smem, const void* src) {
    uint32_t d = (uint32_t)__cvta_generic_to_shared(dst_smem);
    asm volatile("cp.async.cg.shared.global [%0],[%1],16;" :: "r"(d), "l"(src));
}
__device__ __forceinline__ void cp_commit() {
    asm volatile("cp.async.commit_group;");
}
template<int N> __device__ __forceinline__ void cp_wait() {
    asm volatile("cp.async.wait_group %0;" :: "n"(N));
}

// ---------------------------------------------------------------------------
// Prep kernel: 4 sub-CTAs per (f,k) (512 CTAs). Builds 1D tables + ratio r
// (sub 0 writes them), non-atomic partial integration sums, zeroes out.
// ---------------------------------------------------------------------------
__global__ __launch_bounds__(256)
void prep_kernel(const float* __restrict__ qw,
                 const float* __restrict__ mu_lat, const float* __restrict__ ls_lat,
                 const float* __restrict__ mu_lon, const float* __restrict__ ls_lon,
                 const float* __restrict__ mu_lev, const float* __restrict__ ls_lev,
                 const float* __restrict__ lt_time,
                 float* __restrict__ out)
{
    const int bid = blockIdx.x;
    const int fk  = bid >> 2;
    const int sub = bid & 3;
    const int tid = threadIdx.x;
    __shared__ float s_lat[NY], s_lon[NX], s_lev[NP];
    __shared__ float s_part[8];

    // Zero this CTA's slice of out (512 CTAs x 16 = 8192 floats)
    if (tid < 16) out[bid*16 + tid] = 0.f;

    if (tid < NY) {
        float c = -1.f + 2.f * (float)tid / (float)(NY - 1);
        float z = (c - mu_lat[fk]) / expf(ls_lat[fk]);
        float v = expf(-0.5f * z * z);
        s_lat[tid] = v;
        if (sub == 0) g_klat[fk*NY + tid] = v;
    } else if (tid < 32) {
        int x = tid - 16;
        float c = -1.f + 2.f * (float)x / (float)(NX - 1);
        float z = (c - mu_lon[fk]) / expf(ls_lon[fk]);
        float v = expf(-0.5f * z * z);
        s_lon[x] = v;
        if (sub == 0) g_klon[fk*NX + x] = v;
    } else if (tid < 64) {
        int p = tid - 32;
        float c = -1.f + 2.f * (float)p / (float)(NP - 1);
        float z = (c - mu_lev[fk]) / expf(ls_lev[fk]);
        float v = expf(-0.5f * z * z);
        s_lev[p] = v;
        if (sub == 0) g_klev[fk*NP + p] = v;
    }
    float tau = expf(lt_time[fk]) + 1e-6f;
    float r = expf(-1.f / tau);
    if (sub == 0 && tid == 0) g_r[fk] = r;
    __syncthreads();

    // Partial integration over this sub-CTA's 2048 of 8192 points
    const float4* q4 = (const float4*)qw;
    float local = 0.f;
    #pragma unroll 2
    for (int it = 0; it < 8; ++it) {
        int idx = sub*2048 + it*256 + tid;  // point index
        float4 q0 = q4[idx*2];
        float4 q1 = q4[idx*2 + 1];
        float s = q1.w;
        s = fmaf(s, r, q1.z); s = fmaf(s, r, q1.y); s = fmaf(s, r, q1.x);
        s = fmaf(s, r, q0.w); s = fmaf(s, r, q0.z); s = fmaf(s, r, q0.y);
        s = fmaf(s, r, q0.x);
        int p = idx & 31, x = (idx >> 5) & 15, y = idx >> 9;
        local += s * (s_lat[y] * s_lon[x] * s_lev[p]);
    }
    #pragma unroll
    for (int o = 16; o; o >>= 1) local += __shfl_xor_sync(0xffffffffu, local, o);
    if ((tid & 31) == 0) s_part[tid >> 5] = local;
    __syncthreads();
    if (tid == 0) {
        float s = 0.f;
        #pragma unroll
        for (int w = 0; w < 8; ++w) s += s_part[w];
        g_ipart[bid] = s;     // non-atomic partial; feat sums the 4
    }
}

// ---------------------------------------------------------------------------
// Main kernel: grid = NB*NF*CHUNKS (2048 CTAs, 256 threads).
// 4-stage per-thread cp.async pipeline: each thread stages exactly the 64 B
// (2x16B patch + 2x16B qw) it will consume -> no barriers in the mainloop,
// 12-16 LDGSTS outstanding per thread, zero registers held for loads.
// Thread layout: p = tid & 31 constant per thread -> klev in epilogue.
// Inner math: packed Horner over t (geometric ktime) for 8 k-pairs.
// ---------------------------------------------------------------------------
__global__ __launch_bounds__(256, 3)
void feat_kernel(const float* __restrict__ patch,
                 const float* __restrict__ qw,
                 float* __restrict__ out)
{
    extern __shared__ __align__(16) char smem[];
    float4* sb_p  = (float4*)(smem + SB_P_OFF);   // [STAGES][2][256]
    float4* sb_q  = (float4*)(smem + SB_Q_OFF);   // [STAGES][2][256]
    float*  s_cl  = (float*)(smem + S_CL_OFF);
    float*  s_r2  = (float*)(smem + S_R2_OFF);
    float*  s_red = (float*)(smem + S_RED_OFF);

    const int bid   = blockIdx.x;
    const int bf    = bid & (NB*NF - 1);
    const int chunk = bid >> 9;
    const int f     = bf & (NF - 1);
    const int tid   = threadIdx.x;

    const float4* pb = (const float4*)(patch + (size_t)bf * VOL)
                       + (size_t)chunk * (PTS*2);
    const float4* qb = (const float4*)qw + (size_t)chunk * (PTS*2);

    // Prologue: stage first STAGES iterations (one commit each)
    #pragma unroll
    for (int s = 0; s < STAGES; ++s) {
        int il = s*256 + tid;
        cp16(&sb_p[(s*2+0)*256 + tid], pb + il*2);
        cp16(&sb_p[(s*2+1)*256 + tid], pb + il*2 + 1);
        cp16(&sb_q[(s*2+0)*256 + tid], qb + il*2);
        cp16(&sb_q[(s*2+1)*256 + tid], qb + il*2 + 1);
        cp_commit();
    }

    // Combined lat*lon table for this f, this chunk's yx range
    for (int i = tid; i < YXC*NK; i += 256) {
        int k   = i & 15;
        int yx  = chunk*YXC + (i >> 4);
        s_cl[i] = g_klat[(f*NK + k)*NY + (yx >> 4)] * g_klon[(f*NK + k)*NX + (yx & 15)];
    }
    if (tid < 16) s_r2[tid] = g_r[f*NK + tid];

    u64 acc[8];
    #pragma unroll
    for (int kp = 0; kp < 8; ++kp) acc[kp] = 0ull;
    __syncthreads();   // s_cl / s_r2 visible

    const ulonglong2* r2v = (const ulonglong2*)s_r2;   // 4 packed-pair pairs

    #pragma unroll
    for (int j = 0; j < JITER; ++j) {
        cp_wait<STAGES-1>();     // this thread's group j done
        const int slot = j & (STAGES-1);

        float4 a0 = sb_p[(slot*2+0)*256 + tid];
        float4 a1 = sb_p[(slot*2+1)*256 + tid];
        float4 q0 = sb_q[(slot*2+0)*256 + tid];
        float4 q1 = sb_q[(slot*2+1)*256 + tid];

        float wp0 = a0.x*q0.x, wp1 = a0.y*q0.y, wp2 = a0.z*q0.z, wp3 = a0.w*q0.w;
        float wp4 = a1.x*q1.x, wp5 = a1.y*q1.y, wp6 = a1.z*q1.z, wp7 = a1.w*q1.w;

        // Stage iteration j+STAGES into the freed slot (a0..q1 consumed above)
        const int jn = j + STAGES;
        if (jn < JITER) {
            int il = jn*256 + tid;
            cp16(&sb_p[(slot*2+0)*256 + tid], pb + il*2);
            cp16(&sb_p[(slot*2+1)*256 + tid], pb + il*2 + 1);
            cp16(&sb_q[(slot*2+0)*256 + tid], qb + il*2);
            cp16(&sb_q[(slot*2+1)*256 + tid], qb + il*2 + 1);
        }
        cp_commit();             // keep per-thread group counting aligned

        u64 w[8];
        w[0] = pk2(wp0, wp0); w[1] = pk2(wp1, wp1);
        w[2] = pk2(wp2, wp2); w[3] = pk2(wp3, wp3);
        w[4] = pk2(wp4, wp4); w[5] = pk2(wp5, wp5);
        w[6] = pk2(wp6, wp6); w[7] = pk2(wp7, wp7);

        const int il = j*256 + tid;
        const ulonglong2* cl2 = (const ulonglong2*)(s_cl + (il >> 5) * NK);

        #pragma unroll
        for (int h = 0; h < 4; ++h) {           // LDS.128 broadcast pairs
            ulonglong2 rr = r2v[h];
            ulonglong2 cc = cl2[h];
            u64 s0 = w[7], s1 = w[7];
            #pragma unroll
            for (int t = 6; t >= 0; --t) {
                s0 = fma2(s0, rr.x, w[t]);
                s1 = fma2(s1, rr.y, w[t]);
            }
            acc[2*h]   = fma2(s0, cc.x, acc[2*h]);
            acc[2*h+1] = fma2(s1, cc.y, acc[2*h+1]);
        }
    }

    // Epilogue: apply klev (per-thread constant p), reduce 256 -> 1 per k,
    // scale by 1/integrated, atomically accumulate into out.
    const int p = tid & 31;
    float v[16];
    #pragma unroll
    for (int kp = 0; kp < 8; ++kp) {
        int k0 = f*NK + 2*kp;
        u64 kv2 = pk2(g_klev[k0*NP + p], g_klev[(k0+1)*NP + p]);
        float2 t2 = up2(mul2(acc[kp], kv2));
        v[2*kp]   = t2.x;
        v[2*kp+1] = t2.y;
    }
    #pragma unroll
    for (int kk = 0; kk < 16; ++kk) {
        #pragma unroll
        for (int o = 16; o; o >>= 1) v[kk] += __shfl_xor_sync(0xffffffffu, v[kk], o);
    }
    const int lane = tid & 31, wrp = tid >> 5;
    if (lane == 0) {
        #pragma unroll
        for (int kk = 0; kk < 16; ++kk) s_red[wrp*NK + kk] = v[kk];
    }
    __syncthreads();
    if (tid < NK) {
        float s = 0.f;
        #pragma unroll
        for (int w8 = 0; w8 < 8; ++w8) s += s_red[w8*NK + tid];
        const int fk = f*NK + tid;
        float integ = g_ipart[fk*4] + g_ipart[fk*4+1] + g_ipart[fk*4+2] + g_ipart[fk*4+3];
        atomicAdd(&out[(size_t)(bf >> 3) * (NF*NK) + fk],
                  s * (1.f / (integ + 1e-4f)));
    }
}

// ---------------------------------------------------------------------------
// Launch. Inputs (metadata order): patch, quadweights, mu_lat, logsigma_lat,
// mu_lon, logsigma_lon, mu_lev, logsigma_lev, logtau_time.
// ---------------------------------------------------------------------------
extern "C" void kernel_launch(void* const* d_in, const int* in_sizes, int n_in,
                              void* d_out, int out_size)
{
    (void)in_sizes; (void)n_in; (void)out_size;
    const float* patch  = (const float*)d_in[0];
    const float* qw     = (const float*)d_in[1];
    const float* mu_lat = (const float*)d_in[2];
    const float* ls_lat = (const float*)d_in[3];
    const float* mu_lon = (const float*)d_in[4];
    const float* ls_lon = (const float*)d_in[5];
    const float* mu_lev = (const float*)d_in[6];
    const float* ls_lev = (const float*)d_in[7];
    const float* lt     = (const float*)d_in[8];
    float* out = (float*)d_out;

    static bool attr_set = false;
    if (!attr_set) {
        cudaFuncSetAttribute(feat_kernel,
                             cudaFuncAttributeMaxDynamicSharedMemorySize, SMEM_BYTES);
        attr_set = true;
    }

    prep_kernel<<<NF*NK*4, 256>>>(qw, mu_lat, ls_lat, mu_lon, ls_lon,
                                  mu_lev, ls_lev, lt, out);
    feat_kernel<<<NB*NF*CHUNKS, 256, SMEM_BYTES>>>(patch, qw, out);
}

// round 6
// speedup vs baseline: 2.1110x; 2.1110x over previous
#include <cuda_runtime.h>
#include <cstdint>

// Problem constants
#define NF 8
#define NK 16
#define NY 16
#define NX 16
#define NP 32
#define NT 8
#define NB 64
#define VOL (NY*NX*NP*NT)       // 65536 per (b,f)
#define COLS (NY*NX*NP)         // 8192 (y,x,p) points per (b,f)
#define CHUNKS 8
#define PTS (COLS/CHUNKS)       // 1024 points per chunk
#define JITER (PTS/256)         // 4 mainloop iterations
#define YXC (PTS/NP)            // 32 yx per chunk
#define BGROUPS (NB/2)          // 32 (two batches per CTA)

// Precomputed tables (device globals — no allocation allowed)
__device__ float g_klat[NF*NK*NY];
__device__ float g_klon[NF*NK*NX];
__device__ float g_klev[NF*NK*NP];
__device__ float g_r[NF*NK];          // geometric ratio exp(-1/tau)
__device__ float g_ipart[NF*NK*8];    // 8 non-atomic integration partials per (f,k)

using u64 = unsigned long long;

// Packed f32x2 helpers (B300 packed fp32 pipe)
__device__ __forceinline__ u64 pk2(float lo, float hi) {
    u64 r; asm("mov.b64 %0,{%1,%2};" : "=l"(r) : "f"(lo), "f"(hi)); return r;
}
__device__ __forceinline__ u64 fma2(u64 a, u64 b, u64 c) {
    u64 d; asm("fma.rn.f32x2 %0,%1,%2,%3;" : "=l"(d) : "l"(a), "l"(b), "l"(c)); return d;
}
__device__ __forceinline__ u64 mul2(u64 a, u64 b) {
    u64 d; asm("mul.rn.f32x2 %0,%1,%2;" : "=l"(d) : "l"(a), "l"(b)); return d;
}
__device__ __forceinline__ float2 up2(u64 a) {
    float2 v; asm("mov.b64 {%0,%1},%2;" : "=f"(v.x), "=f"(v.y) : "l"(a)); return v;
}

__device__ __forceinline__ int bitrev5(int l) {
    return ((l & 1) << 4) | ((l & 2) << 2) | (l & 4) | ((l & 8) >> 2) | ((l >> 4) & 1);
}

// ---------------------------------------------------------------------------
// Prep kernel: 8 sub-CTAs per (f,k) (1024 CTAs). Builds 1D tables + ratio r
// (sub 0 writes them), non-atomic partial integration sums, zeroes out.
// ---------------------------------------------------------------------------
__global__ __launch_bounds__(256)
void prep_kernel(const float* __restrict__ qw,
                 const float* __restrict__ mu_lat, const float* __restrict__ ls_lat,
                 const float* __restrict__ mu_lon, const float* __restrict__ ls_lon,
                 const float* __restrict__ mu_lev, const float* __restrict__ ls_lev,
                 const float* __restrict__ lt_time,
                 float* __restrict__ out)
{
    const int bid = blockIdx.x;
    const int fk  = bid >> 3;
    const int sub = bid & 7;
    const int tid = threadIdx.x;
    __shared__ float s_lat[NY], s_lon[NX], s_lev[NP];
    __shared__ float s_part[8];

    // Zero this CTA's slice of out (1024 CTAs x 8 = 8192 floats)
    if (tid < 8) out[bid*8 + tid] = 0.f;

    if (tid < NY) {
        float c = -1.f + 2.f * (float)tid / (float)(NY - 1);
        float z = (c - mu_lat[fk]) / expf(ls_lat[fk]);
        float v = expf(-0.5f * z * z);
        s_lat[tid] = v;
        if (sub == 0) g_klat[fk*NY + tid] = v;
    } else if (tid < 32) {
        int x = tid - 16;
        float c = -1.f + 2.f * (float)x / (float)(NX - 1);
        float z = (c - mu_lon[fk]) / expf(ls_lon[fk]);
        float v = expf(-0.5f * z * z);
        s_lon[x] = v;
        if (sub == 0) g_klon[fk*NX + x] = v;
    } else if (tid < 64) {
        int p = tid - 32;
        float c = -1.f + 2.f * (float)p / (float)(NP - 1);
        float z = (c - mu_lev[fk]) / expf(ls_lev[fk]);
        float v = expf(-0.5f * z * z);
        s_lev[p] = v;
        if (sub == 0) g_klev[fk*NP + p] = v;
    }
    float tau = expf(lt_time[fk]) + 1e-6f;
    float r = expf(-1.f / tau);
    if (sub == 0 && tid == 0) g_r[fk] = r;
    __syncthreads();

    // Partial integration over this sub-CTA's 1024 of 8192 points
    const float4* q4 = (const float4*)qw;
    float local = 0.f;
    #pragma unroll
    for (int it = 0; it < 4; ++it) {
        int idx = sub*1024 + it*256 + tid;  // point index
        float4 q0 = q4[idx*2];
        float4 q1 = q4[idx*2 + 1];
        float s = q1.w;
        s = fmaf(s, r, q1.z); s = fmaf(s, r, q1.y); s = fmaf(s, r, q1.x);
        s = fmaf(s, r, q0.w); s = fmaf(s, r, q0.z); s = fmaf(s, r, q0.y);
        s = fmaf(s, r, q0.x);
        int p = idx & 31, x = (idx >> 5) & 15, y = idx >> 9;
        local += s * (s_lat[y] * s_lon[x] * s_lev[p]);
    }
    #pragma unroll
    for (int o = 16; o; o >>= 1) local += __shfl_xor_sync(0xffffffffu, local, o);
    if ((tid & 31) == 0) s_part[tid >> 5] = local;
    __syncthreads();
    if (tid == 0) {
        float s = 0.f;
        #pragma unroll
        for (int w = 0; w < 8; ++w) s += s_part[w];
        g_ipart[bid] = s;     // non-atomic partial; feat sums the 8
    }
}

// ---------------------------------------------------------------------------
// Main kernel: grid = NF*CHUNKS*BGROUPS (2048 CTAs, 256 threads, 2 CTAs/SM).
// Each CTA: one f, one chunk (1/8 of the (y,x,p) points), TWO batches b0,b1.
// qw chunk cached once in smem (deinterleaved, conflict-free LDS.128) ->
// mainloop does only 4 patch LDG.128 per iter; qw L2 traffic halves vs G=1.
// p = tid & 31 constant per thread -> klev applied in epilogue.
// Inner math: packed Horner over t (geometric ktime) for 8 k-pairs x 2 b.
// Epilogue: 31-shfl recursive-halving transpose reduction per warp.
// ---------------------------------------------------------------------------
__global__ __launch_bounds__(256, 2)
void feat_kernel(const float* __restrict__ patch,
                 const float* __restrict__ qw,
                 float* __restrict__ out)
{
    const int bid   = blockIdx.x;
    const int f     = bid & (NF - 1);
    const int chunk = (bid >> 3) & (CHUNKS - 1);
    const int bg    = bid >> 6;            // 0..31
    const int tid   = threadIdx.x;
    const int lane  = tid & 31, wrp = tid >> 5;

    __shared__ __align__(16) float4 sqA[PTS];       // 16 KB
    __shared__ __align__(16) float4 sqB[PTS];       // 16 KB
    __shared__ __align__(16) float  s_cl[YXC*NK];   // 2 KB
    __shared__ float s_red[8*32];                   // 1 KB

    // Cache this chunk's quadweights in smem, deinterleaved (t0-3 / t4-7)
    const float4* qb = (const float4*)qw + (size_t)chunk * (PTS*2);
    for (int i = tid; i < PTS; i += 256) {
        sqA[i] = qb[2*i];
        sqB[i] = qb[2*i + 1];
    }

    // Combined lat*lon table for this f, this chunk's yx range
    for (int i = tid; i < YXC*NK; i += 256) {
        int k  = i & 15;
        int yx = chunk*YXC + (i >> 4);
        s_cl[i] = g_klat[(f*NK + k)*NY + (yx >> 4)] * g_klon[(f*NK + k)*NX + (yx & 15)];
    }

    // Geometric ratios (hoisted into registers; broadcast LDG, L2-resident)
    u64 r2[8], acc0[8], acc1[8];
    #pragma unroll
    for (int kp = 0; kp < 8; ++kp) {
        int k0 = f*NK + 2*kp;
        r2[kp] = pk2(g_r[k0], g_r[k0+1]);
        acc0[kp] = 0ull;
        acc1[kp] = 0ull;
    }
    __syncthreads();

    const float4* pb0 = (const float4*)(patch + (size_t)(bg*2*NF + f) * VOL)
                        + (size_t)chunk * (PTS*2);
    const float4* pb1 = pb0 + (size_t)NF * (VOL/4);   // next batch, same f

    #pragma unroll
    for (int j = 0; j < JITER; ++j) {
        const int il = j*256 + tid;       // local point index within chunk
        float4 a0 = pb0[il*2];
        float4 a1 = pb0[il*2 + 1];
        float4 c0 = pb1[il*2];
        float4 c1 = pb1[il*2 + 1];
        float4 q0 = sqA[il];
        float4 q1 = sqB[il];

        // Weighted patch values, both batches
        u64 wA[8], wB[8];
        {
            float t0 = a0.x*q0.x, t1 = a0.y*q0.y, t2 = a0.z*q0.z, t3 = a0.w*q0.w;
            float t4 = a1.x*q1.x, t5 = a1.y*q1.y, t6 = a1.z*q1.z, t7 = a1.w*q1.w;
            wA[0]=pk2(t0,t0); wA[1]=pk2(t1,t1); wA[2]=pk2(t2,t2); wA[3]=pk2(t3,t3);
            wA[4]=pk2(t4,t4); wA[5]=pk2(t5,t5); wA[6]=pk2(t6,t6); wA[7]=pk2(t7,t7);
        }
        {
            float t0 = c0.x*q0.x, t1 = c0.y*q0.y, t2 = c0.z*q0.z, t3 = c0.w*q0.w;
            float t4 = c1.x*q1.x, t5 = c1.y*q1.y, t6 = c1.z*q1.z, t7 = c1.w*q1.w;
            wB[0]=pk2(t0,t0); wB[1]=pk2(t1,t1); wB[2]=pk2(t2,t2); wB[3]=pk2(t3,t3);
            wB[4]=pk2(t4,t4); wB[5]=pk2(t5,t5); wB[6]=pk2(t6,t6); wB[7]=pk2(t7,t7);
        }

        const u64* cl = (const u64*)(s_cl + (il >> 5) * NK);  // warp-uniform

        #pragma unroll
        for (int kp = 0; kp < 8; ++kp) {
            u64 rr = r2[kp];
            u64 cc = cl[kp];
            u64 s0 = wA[7], s1 = wB[7];
            #pragma unroll
            for (int t = 6; t >= 0; --t) {
                s0 = fma2(s0, rr, wA[t]);
                s1 = fma2(s1, rr, wB[t]);
            }
            acc0[kp] = fma2(s0, cc, acc0[kp]);
            acc1[kp] = fma2(s1, cc, acc1[kp]);
        }
    }

    // Epilogue: apply klev (per-thread p = lane), build 32 values
    // (k 0..15 batch b0, k 0..15 batch b1), transpose-reduce with 31 shfls.
    float cur[32];
    #pragma unroll
    for (int kp = 0; kp < 8; ++kp) {
        int k0 = f*NK + 2*kp;
        u64 kv2 = pk2(g_klev[k0*NP + lane], g_klev[(k0+1)*NP + lane]);
        float2 t0 = up2(mul2(acc0[kp], kv2));
        float2 t1 = up2(mul2(acc1[kp], kv2));
        cur[2*kp]      = t0.x;  cur[2*kp + 1]      = t0.y;
        cur[16 + 2*kp] = t1.x;  cur[16 + 2*kp + 1] = t1.y;
    }
    // Recursive-halving reduce: lane L ends holding total of value bitrev5(L)
    #pragma unroll
    for (int s = 0; s < 5; ++s) {
        const int stride = 1 << s;
        const int nh = 16 >> s;
        const bool hi = (lane >> s) & 1;
        #pragma unroll
        for (int i = 0; i < nh; ++i) {
            float send = hi ? cur[i] : cur[i + nh];
            float keep = hi ? cur[i + nh] : cur[i];
            cur[i] = keep + __shfl_xor_sync(0xffffffffu, send, stride);
        }
    }
    s_red[wrp*32 + bitrev5(lane)] = cur[0];
    __syncthreads();

    if (tid < 32) {
        float s = 0.f;
        #pragma unroll
        for (int w8 = 0; w8 < 8; ++w8) s += s_red[w8*32 + tid];
        const int k  = tid & 15;
        const int b  = bg*2 + (tid >> 4);
        const int fk = f*NK + k;
        float integ = 0.f;
        #pragma unroll
        for (int i = 0; i < 8; ++i) integ += g_ipart[fk*8 + i];
        atomicAdd(&out[(size_t)b * (NF*NK) + fk], s * (1.f / (integ + 1e-4f)));
    }
}

// ---------------------------------------------------------------------------
// Launch. Inputs (metadata order): patch, quadweights, mu_lat, logsigma_lat,
// mu_lon, logsigma_lon, mu_lev, logsigma_lev, logtau_time.
// ---------------------------------------------------------------------------
extern "C" void kernel_launch(void* const* d_in, const int* in_sizes, int n_in,
                              void* d_out, int out_size)
{
    (void)in_sizes; (void)n_in; (void)out_size;
    const float* patch  = (const float*)d_in[0];
    const float* qw     = (const float*)d_in[1];
    const float* mu_lat = (const float*)d_in[2];
    const float* ls_lat = (const float*)d_in[3];
    const float* mu_lon = (const float*)d_in[4];
    const float* ls_lon = (const float*)d_in[5];
    const float* mu_lev = (const float*)d_in[6];
    const float* ls_lev = (const float*)d_in[7];
    const float* lt     = (const float*)d_in[8];
    float* out = (float*)d_out;

    prep_kernel<<<NF*NK*8, 256>>>(qw, mu_lat, ls_lat, mu_lon, ls_lon,
                                  mu_lev, ls_lev, lt, out);
    feat_kernel<<<NF*CHUNKS*BGROUPS, 256>>>(patch, qw, out);
}